// round 16
// baseline (speedup 1.0000x reference)
#include <cuda_runtime.h>
#include <cuda_bf16.h>

#define LN_EPS 1e-5f

// Static scratch for the precomputed pos+type LayerNorm rows [T, H].
// T=128, H=768 here; sized with headroom. Static __device__ array —
// not a runtime allocation, allowed by harness rules.
__device__ float g_ptl[262144];

static __device__ __forceinline__ float warp_sum(float v) {
#pragma unroll
    for (int o = 16; o; o >>= 1) v += __shfl_xor_sync(0xffffffffu, v, o);
    return v;
}

// ---------------------------------------------------------------------------
// Kernel A: ptl[t] = LN(pos[t] + type_emb[t>=V]) * eg + eb       (T blocks)
// ---------------------------------------------------------------------------
__global__ void __launch_bounds__(192)
pos_type_ln_kernel(
    const float* __restrict__ pos,   // [T, H]
    const float* __restrict__ typ,   // [2, H]
    const float* __restrict__ eg, const float* __restrict__ eb,
    int V, int H)
{
    const int t = blockIdx.x;
    const int l = threadIdx.x;       // 0..191, one float4 per lane

    const float4 pp = ((const float4*)(pos + (size_t)t * (size_t)H))[l];
    const float4 tt = ((const float4*)(typ + ((t >= V) ? (size_t)H : (size_t)0)))[l];
    const float4 p  = make_float4(pp.x + tt.x, pp.y + tt.y, pp.z + tt.z, pp.w + tt.w);

    float sp  = p.x + p.y + p.z + p.w;
    float ssp = p.x * p.x + p.y * p.y + p.z * p.z + p.w * p.w;
    sp = warp_sum(sp); ssp = warp_sum(ssp);

    __shared__ float2 red[6];
    const int w = l >> 5;
    if ((l & 31) == 0) red[w] = make_float2(sp, ssp);
    __syncthreads();

    float2 r0 = red[0], r1 = red[1], r2 = red[2];
    float2 r3 = red[3], r4 = red[4], r5 = red[5];
    sp  = ((r0.x + r1.x) + (r2.x + r3.x)) + (r4.x + r5.x);
    ssp = ((r0.y + r1.y) + (r2.y + r3.y)) + (r4.y + r5.y);

    const float invH = 1.0f / (float)H;
    const float mup = sp * invH;
    const float vp  = fmaf(-mup, mup, ssp * invH);
    const float rp  = rsqrtf(vp + LN_EPS);

    const float4 eg4 = ((const float4*)eg)[l];
    const float4 eb4 = ((const float4*)eb)[l];
    float4 r;
    r.x = (p.x - mup) * rp * eg4.x + eb4.x;
    r.y = (p.y - mup) * rp * eg4.y + eb4.y;
    r.z = (p.z - mup) * rp * eg4.z + eb4.z;
    r.w = (p.w - mup) * rp * eg4.w + eb4.w;
    ((float4*)(g_ptl + (size_t)t * (size_t)H))[l] = r;
}

// ---------------------------------------------------------------------------
// Kernel B: out[b,t] = LN(gather)*gamma+beta + ptl[t]         (B*T blocks)
// 5 streams instead of 8; 2 reduce accumulators instead of 4. Epilogue
// operand loads issued BEFORE the barrier so they drain under the reduce.
// ---------------------------------------------------------------------------
__global__ void __launch_bounds__(192, 10)
prev_embedding_kernel(
    const float* __restrict__ cv,    // [V, H]
    const float* __restrict__ ocr,   // [B, N, H]
    const int*   __restrict__ ids,   // [B, T]
    const float* __restrict__ cvg, const float* __restrict__ cvb,
    const float* __restrict__ og,  const float* __restrict__ ob,
    float* __restrict__ out,         // [B, T, H]
    int V, int N, int T, int H)
{
    const int t  = blockIdx.x;
    const int b  = blockIdx.y;
    const int bt = b * T + t;
    const int l  = threadIdx.x;      // 0..191

    const int id = __ldg(ids + bt);
    const float* src;
    const float* gam;
    const float* bet;
    if (id >= V) {
        int oi = id - V;
        oi = max(0, min(oi, N - 1));
        src = ocr + ((size_t)b * (size_t)N + (size_t)oi) * (size_t)H;
        gam = og; bet = ob;
    } else {
        int ci = max(0, min(id, V - 1));
        src = cv + (size_t)ci * (size_t)H;
        gam = cvg; bet = cvb;
    }

    // Front-batch all loads: gather + epilogue operands (the latter are
    // independent of the reduce; their latency hides under shuffles+barrier).
    const float4 a   = ((const float4*)src)[l];
    const float4 g4  = ((const float4*)gam)[l];
    const float4 b4  = ((const float4*)bet)[l];
    const float4 pt4 = ((const float4*)(g_ptl + (size_t)t * (size_t)H))[l];

    float sa  = a.x + a.y + a.z + a.w;
    float ssa = a.x * a.x + a.y * a.y + a.z * a.z + a.w * a.w;
    sa = warp_sum(sa); ssa = warp_sum(ssa);

    __shared__ float2 red[6];
    const int w = l >> 5;
    if ((l & 31) == 0) red[w] = make_float2(sa, ssa);
    __syncthreads();

    float2 r0 = red[0], r1 = red[1], r2 = red[2];
    float2 r3 = red[3], r4 = red[4], r5 = red[5];
    sa  = ((r0.x + r1.x) + (r2.x + r3.x)) + (r4.x + r5.x);
    ssa = ((r0.y + r1.y) + (r2.y + r3.y)) + (r4.y + r5.y);

    const float invH = 1.0f / (float)H;
    const float mua = sa * invH;
    const float va  = fmaf(-mua, mua, ssa * invH);
    const float ra  = rsqrtf(va + LN_EPS);

    float4 r;
    r.x = (a.x - mua) * ra * g4.x + b4.x + pt4.x;
    r.y = (a.y - mua) * ra * g4.y + b4.y + pt4.y;
    r.z = (a.z - mua) * ra * g4.z + b4.z + pt4.z;
    r.w = (a.w - mua) * ra * g4.w + b4.w + pt4.w;
    ((float4*)(out + (size_t)bt * (size_t)H))[l] = r;
}

extern "C" void kernel_launch(void* const* d_in, const int* in_sizes, int n_in,
                              void* d_out, int out_size) {
    const float* cv  = (const float*)d_in[0];
    const float* ocr = (const float*)d_in[1];
    const int*   ids = (const int*)d_in[2];
    const float* cvg = (const float*)d_in[3];
    const float* cvb = (const float*)d_in[4];
    const float* og  = (const float*)d_in[5];
    const float* ob  = (const float*)d_in[6];
    const float* pos = (const float*)d_in[7];
    const float* typ = (const float*)d_in[8];
    const float* eg  = (const float*)d_in[9];
    const float* eb  = (const float*)d_in[10];
    float* out = (float*)d_out;

    const int H  = in_sizes[3];
    const int V  = in_sizes[0] / H;
    const int T  = in_sizes[7] / H;
    const int BT = in_sizes[2];       // B * T
    const int B  = BT / T;
    const int N  = in_sizes[1] / (B * H);

    // Kernel A: tiny precompute of the batch-invariant pos+type LN rows.
    pos_type_ln_kernel<<<T, H / 4>>>(pos, typ, eg, eb, V, H);

    // Kernel B: gather + LN + add (stream-thin hot kernel).
    dim3 grid(T, B);
    prev_embedding_kernel<<<grid, H / 4>>>(
        cv, ocr, ids, cvg, cvb, og, ob, out, V, N, T, H);
}